// round 2
// baseline (speedup 1.0000x reference)
#include <cuda_runtime.h>

#define MAX_SEG   4096
#define MAX_NODES 200704
#define CHUNK     512

__device__ int g_counts[MAX_SEG];
__device__ int g_offsets[MAX_SEG];
__device__ int g_cursor[MAX_SEG];
__device__ int g_nidx[MAX_NODES];
__device__ int g_labels[MAX_NODES];
__device__ int g_is32;

// ---------------------------------------------------------------- init
__global__ void k_init(int n_seg) {
    int i = blockIdx.x * blockDim.x + threadIdx.x;
    if (i == 0) g_is32 = 0;
    if (i < n_seg) { g_counts[i] = 0; g_cursor[i] = 0; }
}

// ---------------------------------------------------------------- dtype detect
// View labels as int32 words. If the true dtype is int64 (values < 4096),
// every odd word (high half) is 0. If int32, odd words are labels themselves
// and are almost surely nonzero somewhere. Reading words [0, n) is in-bounds
// under BOTH interpretations (int64 buffer has 2n words, int32 has n).
__global__ void k_detect(const int* __restrict__ l32, int n) {
    int i = blockIdx.x * blockDim.x + threadIdx.x;  // i < n/2
    if (2 * i + 1 < n) {
        if (l32[2 * i + 1] != 0) g_is32 = 1;        // benign race: all write 1
    }
}

// ---------------------------------------------------------------- normalize labels -> int
__global__ void k_convert(const void* __restrict__ labels, int n) {
    int i = blockIdx.x * blockDim.x + threadIdx.x;
    if (i < n) {
        int v = g_is32 ? ((const int*)labels)[i]
                       : (int)((const long long*)labels)[i];
        g_labels[i] = v;
    }
}

// ---------------------------------------------------------------- count
__global__ void k_count(int n) {
    int i = blockIdx.x * blockDim.x + threadIdx.x;
    if (i < n) atomicAdd(&g_counts[g_labels[i]], 1);
}

// ---------------------------------------------------------------- scan (exclusive, n_seg <= 4096)
__global__ void k_scan(int n_seg) {
    __shared__ int sh[1024];
    int t = threadIdx.x;
    int v[4];
    int s = 0;
#pragma unroll
    for (int k = 0; k < 4; k++) {
        int i = t * 4 + k;
        int c = (i < n_seg) ? g_counts[i] : 0;
        v[k] = s;           // exclusive within the 4-group
        s += c;
    }
    sh[t] = s;
    __syncthreads();
    // Hillis-Steele inclusive scan over 1024 per-thread sums
    for (int off = 1; off < 1024; off <<= 1) {
        int add = (t >= off) ? sh[t - off] : 0;
        __syncthreads();
        sh[t] += add;
        __syncthreads();
    }
    int excl = sh[t] - s;   // exclusive prefix of this thread's group
#pragma unroll
    for (int k = 0; k < 4; k++) {
        int i = t * 4 + k;
        if (i < n_seg) g_offsets[i] = excl + v[k];
    }
}

// ---------------------------------------------------------------- scatter node indices (CSR fill)
__global__ void k_scatter(int n) {
    int i = blockIdx.x * blockDim.x + threadIdx.x;
    if (i < n) {
        int l = g_labels[i];
        int p = g_offsets[l] + atomicAdd(&g_cursor[l], 1);
        g_nidx[p] = i;
    }
}

// ---------------------------------------------------------------- per-segment gather + mean
// One block per segment. Threads [0, dim/4) each own one float4 column slice.
// Indices staged through shared memory in CHUNK batches; inner loop unrolled
// x4 for MLP on the fat gather loads.
__global__ void __launch_bounds__(128) k_sum(const float* __restrict__ x,
                                             float* __restrict__ out,
                                             int dim) {
    int seg  = blockIdx.x;
    int tid  = threadIdx.x;
    int dim4 = dim >> 2;               // 120 for dim=480
    int start = g_offsets[seg];
    int cnt   = g_counts[seg];

    __shared__ int sh[CHUNK];
    float4 acc = make_float4(0.f, 0.f, 0.f, 0.f);

    for (int base = 0; base < cnt; base += CHUNK) {
        int m = min(CHUNK, cnt - base);
        __syncthreads();
        for (int i = tid; i < m; i += blockDim.x)
            sh[i] = g_nidx[start + base + i];
        __syncthreads();

        if (tid < dim4) {
            int j = 0;
            for (; j + 4 <= m; j += 4) {
                const float4* p0 = (const float4*)(x + (size_t)sh[j + 0] * dim);
                const float4* p1 = (const float4*)(x + (size_t)sh[j + 1] * dim);
                const float4* p2 = (const float4*)(x + (size_t)sh[j + 2] * dim);
                const float4* p3 = (const float4*)(x + (size_t)sh[j + 3] * dim);
                float4 v0 = p0[tid];
                float4 v1 = p1[tid];
                float4 v2 = p2[tid];
                float4 v3 = p3[tid];
                acc.x += (v0.x + v1.x) + (v2.x + v3.x);
                acc.y += (v0.y + v1.y) + (v2.y + v3.y);
                acc.z += (v0.z + v1.z) + (v2.z + v3.z);
                acc.w += (v0.w + v1.w) + (v2.w + v3.w);
            }
            for (; j < m; j++) {
                float4 v = ((const float4*)(x + (size_t)sh[j] * dim))[tid];
                acc.x += v.x; acc.y += v.y; acc.z += v.z; acc.w += v.w;
            }
        }
    }

    if (tid < dim4) {
        float inv = 1.0f / (float)max(cnt, 1);
        float4 o;
        o.x = acc.x * inv;
        o.y = acc.y * inv;
        o.z = acc.z * inv;
        o.w = acc.w * inv;
        ((float4*)(out + (size_t)seg * dim))[tid] = o;
    }
}

// ---------------------------------------------------------------- launch
extern "C" void kernel_launch(void* const* d_in, const int* in_sizes, int n_in,
                              void* d_out, int out_size) {
    const float* x      = (const float*)d_in[0];
    const void*  labels = d_in[1];
    float*       out    = (float*)d_out;

    int n_nodes = in_sizes[1];
    int dim     = in_sizes[0] / n_nodes;      // 480
    int n_seg   = out_size / dim;             // 4096

    k_init<<<(n_seg + 255) / 256, 256>>>(n_seg);
    k_detect<<<(n_nodes / 2 + 255) / 256, 256>>>((const int*)labels, n_nodes);
    k_convert<<<(n_nodes + 255) / 256, 256>>>(labels, n_nodes);
    k_count<<<(n_nodes + 255) / 256, 256>>>(n_nodes);
    k_scan<<<1, 1024>>>(n_seg);
    k_scatter<<<(n_nodes + 255) / 256, 256>>>(n_nodes);
    k_sum<<<n_seg, 128>>>(x, out, dim);
}

// round 3
// speedup vs baseline: 1.0105x; 1.0105x over previous
#include <cuda_runtime.h>

#define MAX_SEG   4096
#define MAX_NODES 200704
#define CHUNK     512

// All scratch starts zeroed (static init) and is RE-ZEROED at the end of every
// kernel_launch sequence (by k_sum), so each graph replay sees clean state.
__device__ int g_counts[MAX_SEG];
__device__ int g_offsets[MAX_SEG];
__device__ int g_cursor[MAX_SEG];
__device__ int g_nidx[MAX_NODES];
__device__ int g_labels[MAX_NODES];
__device__ int g_det;                 // 1 => labels are int32

// ---------------------------------------------------------------- dtype detect
// View labels as int32 words. If the true dtype is int64 (values < n_seg),
// every odd word (high half) is 0. If int32, odd words are labels and are
// almost surely nonzero somewhere. Reading words [0, n) is in-bounds under
// BOTH interpretations. g_det is zeroed by the previous launch's k_sum.
__global__ void k_detect(const int* __restrict__ l32, int n) {
    int i = blockIdx.x * blockDim.x + threadIdx.x;
    if (2 * i + 1 < n) {
        if (l32[2 * i + 1] != 0) g_det = 1;   // benign race: all write 1
    }
}

// ---------------------------------------------------------------- convert + count
__global__ void k_count(const void* __restrict__ labels, int n) {
    int i = blockIdx.x * blockDim.x + threadIdx.x;
    if (i < n) {
        int v = g_det ? ((const int*)labels)[i]
                      : (int)((const long long*)labels)[i];
        g_labels[i] = v;
        atomicAdd(&g_counts[v], 1);
    }
}

// ---------------------------------------------------------------- scan (exclusive, n_seg <= 4096)
__global__ void k_scan(int n_seg) {
    __shared__ int sh[1024];
    int t = threadIdx.x;
    int v[4];
    int s = 0;
#pragma unroll
    for (int k = 0; k < 4; k++) {
        int i = t * 4 + k;
        int c = (i < n_seg) ? g_counts[i] : 0;
        v[k] = s;           // exclusive within the 4-group
        s += c;
    }
    sh[t] = s;
    __syncthreads();
    for (int off = 1; off < 1024; off <<= 1) {
        int add = (t >= off) ? sh[t - off] : 0;
        __syncthreads();
        sh[t] += add;
        __syncthreads();
    }
    int excl = sh[t] - s;
#pragma unroll
    for (int k = 0; k < 4; k++) {
        int i = t * 4 + k;
        if (i < n_seg) g_offsets[i] = excl + v[k];
    }
}

// ---------------------------------------------------------------- scatter node indices (CSR fill)
__global__ void k_scatter(int n) {
    int i = blockIdx.x * blockDim.x + threadIdx.x;
    if (i < n) {
        int l = g_labels[i];
        int p = g_offsets[l] + atomicAdd(&g_cursor[l], 1);
        g_nidx[p] = i;
    }
}

// ---------------------------------------------------------------- per-segment gather + mean
// One block per segment. Threads [0, dim/4) each own one float4 column slice.
// Indices staged through shared memory; inner loop unrolled x4 for MLP.
// Tail of the kernel re-zeros this segment's scratch for the next replay.
__global__ void __launch_bounds__(128) k_sum(const float* __restrict__ x,
                                             float* __restrict__ out,
                                             int dim) {
    int seg  = blockIdx.x;
    int tid  = threadIdx.x;
    int dim4 = dim >> 2;               // 120 for dim=480
    int start = g_offsets[seg];
    int cnt   = g_counts[seg];

    __shared__ int sh[CHUNK];
    float4 acc = make_float4(0.f, 0.f, 0.f, 0.f);

    for (int base = 0; base < cnt; base += CHUNK) {
        int m = min(CHUNK, cnt - base);
        __syncthreads();
        for (int i = tid; i < m; i += blockDim.x)
            sh[i] = g_nidx[start + base + i];
        __syncthreads();

        if (tid < dim4) {
            int j = 0;
            for (; j + 4 <= m; j += 4) {
                const float4* p0 = (const float4*)(x + (size_t)sh[j + 0] * dim);
                const float4* p1 = (const float4*)(x + (size_t)sh[j + 1] * dim);
                const float4* p2 = (const float4*)(x + (size_t)sh[j + 2] * dim);
                const float4* p3 = (const float4*)(x + (size_t)sh[j + 3] * dim);
                float4 v0 = p0[tid];
                float4 v1 = p1[tid];
                float4 v2 = p2[tid];
                float4 v3 = p3[tid];
                acc.x += (v0.x + v1.x) + (v2.x + v3.x);
                acc.y += (v0.y + v1.y) + (v2.y + v3.y);
                acc.z += (v0.z + v1.z) + (v2.z + v3.z);
                acc.w += (v0.w + v1.w) + (v2.w + v3.w);
            }
            for (; j < m; j++) {
                float4 v = ((const float4*)(x + (size_t)sh[j] * dim))[tid];
                acc.x += v.x; acc.y += v.y; acc.z += v.z; acc.w += v.w;
            }
        }
    }

    if (tid < dim4) {
        float inv = 1.0f / (float)max(cnt, 1);
        float4 o;
        o.x = acc.x * inv;
        o.y = acc.y * inv;
        o.z = acc.z * inv;
        o.w = acc.w * inv;
        ((float4*)(out + (size_t)seg * dim))[tid] = o;
    }

    // self-clean scratch for the next graph replay
    if (tid == 127) {
        g_counts[seg] = 0;
        g_cursor[seg] = 0;
        if (seg == 0) g_det = 0;
    }
}

// ---------------------------------------------------------------- launch
extern "C" void kernel_launch(void* const* d_in, const int* in_sizes, int n_in,
                              void* d_out, int out_size) {
    const float* x      = (const float*)d_in[0];
    const void*  labels = d_in[1];
    float*       out    = (float*)d_out;

    int n_nodes = in_sizes[1];
    int dim     = in_sizes[0] / n_nodes;      // 480
    int n_seg   = out_size / dim;             // 4096

    k_detect<<<(n_nodes / 2 + 255) / 256, 256>>>((const int*)labels, n_nodes);
    k_count<<<(n_nodes + 255) / 256, 256>>>(labels, n_nodes);
    k_scan<<<1, 1024>>>(n_seg);
    k_scatter<<<(n_nodes + 255) / 256, 256>>>(n_nodes);
    k_sum<<<n_seg, 128>>>(x, out, dim);
}

// round 4
// speedup vs baseline: 1.2064x; 1.1938x over previous
#include <cuda_runtime.h>

#define MAX_SEG    4096
#define MAX_NODES  200704
#define C_PER_SEG  4096          // per-segment index capacity (mean load ~49)
#define CHUNK      512

// All scratch starts zeroed (static init) and is re-zeroed at the end of every
// launch sequence (by k_sum), so each graph replay sees clean state.
__device__ int g_cursor[MAX_SEG];
__device__ int g_nidx[MAX_SEG * C_PER_SEG];   // 64 MB strided CSR
__device__ int g_labels[MAX_NODES];
__device__ int g_det;                          // 1 => labels are int32

// ---------------------------------------------------------------- dtype detect
// View labels as int32 words. int64 labels (< n_seg) have all odd words == 0;
// int32 labels put label values in odd words (nonzero somewhere w.h.p.).
// Reading words [0, n) is in-bounds under BOTH interpretations.
__global__ void k_detect(const int* __restrict__ w, int n) {
    int i = blockIdx.x * blockDim.x + threadIdx.x;
    int base = i * 4;
    if (base + 3 < n) {
        int4 v = *(const int4*)(w + base);          // words 4i .. 4i+3
        if ((v.y | v.w) != 0) g_det = 1;            // odd words; benign race
    } else if (base < n) {
        for (int k = base + 1; k < n; k += 2)
            if (w[k] != 0) g_det = 1;
    }
}

// ---------------------------------------------------------------- convert + scatter
__global__ void k_scatter(const void* __restrict__ labels, int n) {
    int i = blockIdx.x * blockDim.x + threadIdx.x;
    if (i < n) {
        int v = g_det ? ((const int*)labels)[i]
                      : (int)((const long long*)labels)[i];
        g_labels[i] = v;
        int p = atomicAdd(&g_cursor[v], 1);
        if (p < C_PER_SEG) g_nidx[v * C_PER_SEG + p] = i;
    }
}

// ---------------------------------------------------------------- per-segment gather + mean
// One block per segment. Threads [0, dim/4) each own one float4 column slice.
// Indices staged through shared memory; inner loop unrolled x4 for MLP.
// If a segment overflowed its capacity (never for realistic inputs), fall back
// to a full label scan — block-uniform branch, fully correct.
__global__ void __launch_bounds__(128) k_sum(const float* __restrict__ x,
                                             float* __restrict__ out,
                                             int dim, int n) {
    int seg  = blockIdx.x;
    int tid  = threadIdx.x;
    int dim4 = dim >> 2;               // 120 for dim=480
    int cnt  = g_cursor[seg];

    __shared__ int sh[CHUNK];
    float4 acc = make_float4(0.f, 0.f, 0.f, 0.f);

    if (cnt <= C_PER_SEG) {
        const int* idx = g_nidx + seg * C_PER_SEG;
        for (int base = 0; base < cnt; base += CHUNK) {
            int m = min(CHUNK, cnt - base);
            __syncthreads();
            for (int i = tid; i < m; i += blockDim.x)
                sh[i] = idx[base + i];
            __syncthreads();

            if (tid < dim4) {
                int j = 0;
                for (; j + 4 <= m; j += 4) {
                    const float4* p0 = (const float4*)(x + (size_t)sh[j + 0] * dim);
                    const float4* p1 = (const float4*)(x + (size_t)sh[j + 1] * dim);
                    const float4* p2 = (const float4*)(x + (size_t)sh[j + 2] * dim);
                    const float4* p3 = (const float4*)(x + (size_t)sh[j + 3] * dim);
                    float4 v0 = p0[tid];
                    float4 v1 = p1[tid];
                    float4 v2 = p2[tid];
                    float4 v3 = p3[tid];
                    acc.x += (v0.x + v1.x) + (v2.x + v3.x);
                    acc.y += (v0.y + v1.y) + (v2.y + v3.y);
                    acc.z += (v0.z + v1.z) + (v2.z + v3.z);
                    acc.w += (v0.w + v1.w) + (v2.w + v3.w);
                }
                for (; j < m; j++) {
                    float4 v = ((const float4*)(x + (size_t)sh[j] * dim))[tid];
                    acc.x += v.x; acc.y += v.y; acc.z += v.z; acc.w += v.w;
                }
            }
        }
    } else {
        // overflow fallback: scan all labels (block-uniform condition per i)
        for (int i = 0; i < n; i++) {
            if (g_labels[i] == seg) {
                if (tid < dim4) {
                    float4 v = ((const float4*)(x + (size_t)i * dim))[tid];
                    acc.x += v.x; acc.y += v.y; acc.z += v.z; acc.w += v.w;
                }
            }
        }
    }

    if (tid < dim4) {
        float inv = 1.0f / (float)max(cnt, 1);
        float4 o;
        o.x = acc.x * inv;
        o.y = acc.y * inv;
        o.z = acc.z * inv;
        o.w = acc.w * inv;
        ((float4*)(out + (size_t)seg * dim))[tid] = o;
    }

    // self-clean scratch for the next graph replay
    if (tid == 127) {
        g_cursor[seg] = 0;
        if (seg == 0) g_det = 0;
    }
}

// ---------------------------------------------------------------- launch
extern "C" void kernel_launch(void* const* d_in, const int* in_sizes, int n_in,
                              void* d_out, int out_size) {
    const float* x      = (const float*)d_in[0];
    const void*  labels = d_in[1];
    float*       out    = (float*)d_out;

    int n_nodes = in_sizes[1];
    int dim     = in_sizes[0] / n_nodes;      // 480
    int n_seg   = out_size / dim;             // 4096

    k_detect<<<(n_nodes / 4 + 255) / 256, 256>>>((const int*)labels, n_nodes);
    k_scatter<<<(n_nodes + 255) / 256, 256>>>(labels, n_nodes);
    k_sum<<<n_seg, 128>>>(x, out, dim, n_nodes);
}

// round 5
// speedup vs baseline: 1.2397x; 1.0276x over previous
#include <cuda_runtime.h>

#define MAX_SEG    4096
#define MAX_NODES  200704
#define C_PER_SEG  4096          // per-segment index capacity (mean load ~49)
#define CHUNK      512

// All scratch starts zeroed (static init) and is re-zeroed at the end of every
// launch sequence (by k_sum), so each graph replay sees clean state.
__device__ int g_cursor[MAX_SEG];
__device__ int g_nidx[MAX_SEG * C_PER_SEG];   // 64 MB strided CSR
__device__ int g_labels[MAX_NODES];

// ---------------------------------------------------------------- convert + scatter
// Dtype detection is fused in, block-locally: view labels as int32 words.
// int64 labels (< n_seg) have all odd words == 0; int32 labels put label
// values in odd words (nonzero somewhere in the first 512 words w.h.p.
// 1-(1/4096)^256). Each block probes the same first 512 words (L2-resident
// after the first block) and reduces via __syncthreads_or -> block-uniform.
__global__ void k_scatter(const void* __restrict__ labels, int n) {
    const int* w = (const int*)labels;
    int tid = threadIdx.x;

    int probe = 2 * tid + 1;                 // odd words 1..511
    int my = (probe < n) ? (w[probe] != 0) : 0;
    int det = __syncthreads_or(my);          // 1 => labels are int32

    int i0 = 2 * (blockIdx.x * blockDim.x + tid);
    int v0 = -1, v1 = -1;
    if (det) {
        if (i0 + 1 < n) {
            int2 p = *(const int2*)(w + i0);
            v0 = p.x; v1 = p.y;
        } else if (i0 < n) {
            v0 = w[i0];
        }
    } else {
        const long long* l = (const long long*)labels;
        if (i0 + 1 < n) {
            longlong2 p = *(const longlong2*)(l + i0);
            v0 = (int)p.x; v1 = (int)p.y;
        } else if (i0 < n) {
            v0 = (int)l[i0];
        }
    }
    if (v0 >= 0) {
        g_labels[i0] = v0;
        int p = atomicAdd(&g_cursor[v0], 1);
        if (p < C_PER_SEG) g_nidx[v0 * C_PER_SEG + p] = i0;
    }
    if (v1 >= 0) {
        g_labels[i0 + 1] = v1;
        int p = atomicAdd(&g_cursor[v1], 1);
        if (p < C_PER_SEG) g_nidx[v1 * C_PER_SEG + p] = i0 + 1;
    }
}

// ---------------------------------------------------------------- per-segment gather + mean
// One block per segment. Threads [0, dim/4) each own one float4 column slice.
// Indices staged through shared memory; inner loop unrolled x4 for MLP.
// If a segment overflowed its capacity (never for realistic inputs), fall back
// to a full label scan — block-uniform branch, fully correct.
__global__ void __launch_bounds__(128) k_sum(const float* __restrict__ x,
                                             float* __restrict__ out,
                                             int dim, int n) {
    int seg  = blockIdx.x;
    int tid  = threadIdx.x;
    int dim4 = dim >> 2;               // 120 for dim=480
    int cnt  = g_cursor[seg];

    __shared__ int sh[CHUNK];
    float4 acc = make_float4(0.f, 0.f, 0.f, 0.f);

    if (cnt <= C_PER_SEG) {
        const int* idx = g_nidx + seg * C_PER_SEG;
        for (int base = 0; base < cnt; base += CHUNK) {
            int m = min(CHUNK, cnt - base);
            __syncthreads();
            for (int i = tid; i < m; i += blockDim.x)
                sh[i] = idx[base + i];
            __syncthreads();

            if (tid < dim4) {
                int j = 0;
                for (; j + 4 <= m; j += 4) {
                    const float4* p0 = (const float4*)(x + (size_t)sh[j + 0] * dim);
                    const float4* p1 = (const float4*)(x + (size_t)sh[j + 1] * dim);
                    const float4* p2 = (const float4*)(x + (size_t)sh[j + 2] * dim);
                    const float4* p3 = (const float4*)(x + (size_t)sh[j + 3] * dim);
                    float4 v0 = p0[tid];
                    float4 v1 = p1[tid];
                    float4 v2 = p2[tid];
                    float4 v3 = p3[tid];
                    acc.x += (v0.x + v1.x) + (v2.x + v3.x);
                    acc.y += (v0.y + v1.y) + (v2.y + v3.y);
                    acc.z += (v0.z + v1.z) + (v2.z + v3.z);
                    acc.w += (v0.w + v1.w) + (v2.w + v3.w);
                }
                for (; j < m; j++) {
                    float4 v = ((const float4*)(x + (size_t)sh[j] * dim))[tid];
                    acc.x += v.x; acc.y += v.y; acc.z += v.z; acc.w += v.w;
                }
            }
        }
    } else {
        // overflow fallback: scan all labels (block-uniform condition per i)
        for (int i = 0; i < n; i++) {
            if (g_labels[i] == seg) {
                if (tid < dim4) {
                    float4 v = ((const float4*)(x + (size_t)i * dim))[tid];
                    acc.x += v.x; acc.y += v.y; acc.z += v.z; acc.w += v.w;
                }
            }
        }
    }

    if (tid < dim4) {
        float inv = 1.0f / (float)max(cnt, 1);
        float4 o;
        o.x = acc.x * inv;
        o.y = acc.y * inv;
        o.z = acc.z * inv;
        o.w = acc.w * inv;
        ((float4*)(out + (size_t)seg * dim))[tid] = o;
    }

    // self-clean scratch for the next graph replay
    if (tid == 127) g_cursor[seg] = 0;
}

// ---------------------------------------------------------------- launch
extern "C" void kernel_launch(void* const* d_in, const int* in_sizes, int n_in,
                              void* d_out, int out_size) {
    const float* x      = (const float*)d_in[0];
    const void*  labels = d_in[1];
    float*       out    = (float*)d_out;

    int n_nodes = in_sizes[1];
    int dim     = in_sizes[0] / n_nodes;      // 480
    int n_seg   = out_size / dim;             // 4096

    k_scatter<<<(n_nodes / 2 + 255) / 256, 256>>>(labels, n_nodes);
    k_sum<<<n_seg, 128>>>(x, out, dim, n_nodes);
}